// round 16
// baseline (speedup 1.0000x reference)
#include <cuda_runtime.h>

// ---------------------------------------------------------------------------
// InteractingLayer fused kernel v5: LDS-minimized
//   - prep kernel emits weights in exact consumption order:
//     g_wt[chunk][e2][mat][j][cT][quad], quad={w(c0,e0),w(c0+1,e0),
//                                             w(c0,e1),w(c0+1,e1)}
//     -> projection w-operands are contiguous LDS.128, 1 wavefront each
//   - x dup-pair rows read as LDS.128 (covers 2 e's)
//   - scores: 2-dp stepping (LDS.128 q/k);  AV: 4-g stepping (float4 scores)
//   - 256 thr/CTA, 2 CTAs/SM, q/k/v/r+ss overlay the staging region
// ---------------------------------------------------------------------------

#define Fd   40
#define Ed   64
#define OUTd 128

#define XD_STRIDE 136
#define CHUNK_E   32
#define WT_CHUNK  16384                 /* floats: 16 e2-blocks x 1024 */
#define QR_STRIDE 132
#define SS_ROW    44
#define SS_HEAD   1764

/* phase-1 (staging/projection) layout */
#define OFF_XD  0                       /* 40*136 = 5440        */
#define OFF_WTS 5440                    /* 16384 -> end 21824   */
/* phase-2 layout (overlays phase-1; acc carried in regs) */
#define OFF_QS  0
#define OFF_KS  (OFF_QS + Fd * QR_STRIDE)
#define OFF_VS  (OFF_KS + Fd * QR_STRIDE)
#define OFF_RS  (OFF_VS + Fd * QR_STRIDE)
#define OFF_SS  (OFF_RS + Fd * QR_STRIDE)      /* 21120, 4*1764=7056 */
#define SMEM_FLOATS (OFF_SS + 4 * SS_HEAD)     /* 28176 -> 112704 B  */
#define SMEM_BYTES  (SMEM_FLOATS * 4)

typedef unsigned long long ull;

__device__ float g_wt[2 * WT_CHUNK];    /* 128 KB, consumption-ordered */

__device__ __forceinline__ ull pk2(float a, float b) {
    ull r; asm("mov.b64 %0, {%1,%2};" : "=l"(r) : "f"(a), "f"(b)); return r;
}
__device__ __forceinline__ void unpk2(ull v, float& a, float& b) {
    asm("mov.b64 {%0,%1}, %2;" : "=f"(a), "=f"(b) : "l"(v));
}
__device__ __forceinline__ ull ffma2(ull a, ull b, ull c) {
    ull d; asm("fma.rn.f32x2 %0, %1, %2, %3;" : "=l"(d) : "l"(a), "l"(b), "l"(c));
    return d;
}

// ---- prep: consumption-ordered transpose ----------------------------------
// dst = c*16384 + e2*1024 + m*256 + j*32 + cT*4 + eo*2 + p
//   c=e>>5, el=e&31, e2=el>>1, eo=el&1 ; col=2cT+16j+p
__global__ void prep_wt_kernel(const float* __restrict__ Wq,
                               const float* __restrict__ Wk,
                               const float* __restrict__ Wv,
                               const float* __restrict__ Wr)
{
    int i = blockIdx.x * blockDim.x + threadIdx.x;   // 0..32767
    int m   = i >> 13;
    int r   = i & 8191;
    int col = r >> 6;
    int e   = r & 63;
    int c   = e >> 5;
    int el  = e & 31;
    int e2  = el >> 1;
    int eo  = el & 1;
    int j   = col >> 4;
    int cT  = (col & 15) >> 1;
    int p   = col & 1;
    const float* Wm = (m == 0) ? Wq : (m == 1) ? Wk : (m == 2) ? Wv : Wr;
    g_wt[c * WT_CHUNK + e2 * 1024 + m * 256 + j * 32 + cT * 4 + eo * 2 + p]
        = Wm[r];
}

// ---- main fused kernel ------------------------------------------------------
__global__ __launch_bounds__(256, 2)
void interacting_layer_kernel(
    const float* __restrict__ x,
    const float* __restrict__ bq, const float* __restrict__ bk,
    const float* __restrict__ bv, const float* __restrict__ br,
    float* __restrict__ out)
{
    extern __shared__ float sm[];
    float* xd  = sm + OFF_XD;
    float* wts = sm + OFF_WTS;
    float* qs  = sm + OFF_QS;
    float* ks  = sm + OFF_KS;
    float* vs  = sm + OFF_VS;
    float* rs  = sm + OFF_RS;
    float* ss  = sm + OFF_SS;

    const int b = blockIdx.x;
    const int t = threadIdx.x;

    // ===== projection setup: 64 threads/matrix, tile 5 rows x 8 col pairs =
    const int mat = t >> 6;
    const int q2  = t & 63;
    const int f0  = (q2 >> 3) * 5;
    const int cT  = q2 & 7;

    const float* myB = (mat == 0) ? bq : (mat == 1) ? bk : (mat == 2) ? bv : br;
    float*       myO = (mat == 0) ? qs : (mat == 1) ? ks : (mat == 2) ? vs : rs;

    ull acc[5][8];
#pragma unroll
    for (int j = 0; j < 8; j++) {
        float b0 = __ldg(myB + 2 * cT + 16 * j);
        float b1 = __ldg(myB + 2 * cT + 16 * j + 1);
        ull bb = pk2(b0, b1);
#pragma unroll
        for (int i = 0; i < 5; i++) acc[i][j] = bb;
    }

    // ===== two weight chunks: stage -> sync -> accumulate -> sync =========
#pragma unroll 1
    for (int c = 0; c < 2; c++) {
        {
            const float4* gw4 = (const float4*)g_wt + c * (WT_CHUNK / 4);
            float4* wt4 = (float4*)wts;
#pragma unroll
            for (int k = 0; k < WT_CHUNK / 4 / 256; k++)     // 16 iters
                wt4[t + k * 256] = gw4[t + k * 256];
            if (c == 0) {
                const float2* x2 = (const float2*)(x + (size_t)b * (Fd * Ed));
#pragma unroll
                for (int k = 0; k < 5; k++) {
                    int i = t + k * 256;                      // 1280 float2
                    int f  = i >> 5;
                    int ep = i & 31;
                    float2 v = x2[i];
                    float4 d;
                    d.x = v.x; d.y = v.x; d.z = v.y; d.w = v.y;
                    *(float4*)(xd + f * XD_STRIDE + ep * 4) = d;
                }
            }
        }
        __syncthreads();

        const float* myW = wts + mat * 256 + cT * 4;
        const float* myX = xd + f0 * XD_STRIDE + c * 64;
#pragma unroll 2
        for (int e2 = 0; e2 < 16; e2++) {
            ulonglong2 xx[5];
#pragma unroll
            for (int i = 0; i < 5; i++)
                xx[i] = *(const ulonglong2*)(myX + i * XD_STRIDE + e2 * 4);
#pragma unroll
            for (int jh = 0; jh < 2; jh++) {
                ulonglong2 w[4];
#pragma unroll
                for (int jj = 0; jj < 4; jj++)
                    w[jj] = *(const ulonglong2*)(myW + e2 * 1024 + (jh * 4 + jj) * 32);
#pragma unroll
                for (int i = 0; i < 5; i++)
#pragma unroll
                    for (int jj = 0; jj < 4; jj++) {
                        acc[i][jh * 4 + jj] = ffma2(xx[i].x, w[jj].x, acc[i][jh * 4 + jj]);
                        acc[i][jh * 4 + jj] = ffma2(xx[i].y, w[jj].y, acc[i][jh * 4 + jj]);
                    }
            }
        }
        __syncthreads();   // after c=1 this also frees xd/wts for overlay
    }

    // ===== write q/k/v/r (overlays staging region) ========================
#pragma unroll
    for (int i = 0; i < 5; i++)
#pragma unroll
        for (int j = 0; j < 8; j++)
            *(ull*)(myO + (f0 + i) * QR_STRIDE + 2 * cT + 16 * j) = acc[i][j];
    __syncthreads();

    // ===== scores: S[h][f][g] = (q.k)/8, 2-dp stepping ====================
    {
        const int h   = t >> 6;
        const int rst = t & 63;
        const int f0s = (rst >> 3) * 5;
        const int g0  = (rst & 7) * 5;

        ull acc2[5][5];
#pragma unroll
        for (int i = 0; i < 5; i++)
#pragma unroll
            for (int j = 0; j < 5; j++) acc2[i][j] = 0ull;

        const float* qb = qs + h * 32;
        const float* kb = ks + h * 32;
#pragma unroll 2
        for (int dp2 = 0; dp2 < 8; dp2++) {
            ulonglong2 qv[5], kv[5];
#pragma unroll
            for (int i = 0; i < 5; i++)
                qv[i] = *(const ulonglong2*)(qb + (f0s + i) * QR_STRIDE + 4 * dp2);
#pragma unroll
            for (int j = 0; j < 5; j++)
                kv[j] = *(const ulonglong2*)(kb + (g0 + j) * QR_STRIDE + 4 * dp2);
#pragma unroll
            for (int i = 0; i < 5; i++)
#pragma unroll
                for (int j = 0; j < 5; j++) {
                    acc2[i][j] = ffma2(qv[i].x, kv[j].x, acc2[i][j]);
                    acc2[i][j] = ffma2(qv[i].y, kv[j].y, acc2[i][j]);
                }
        }
#pragma unroll
        for (int i = 0; i < 5; i++)
#pragma unroll
            for (int j = 0; j < 5; j++) {
                float a0, a1;
                unpk2(acc2[i][j], a0, a1);
                ss[h * SS_HEAD + (f0s + i) * SS_ROW + g0 + j] = (a0 + a1) * 0.125f;
            }
    }
    __syncthreads();

    // ===== softmax: 1 thread per row (160 rows), float4 row I/O ===========
    if (t < 160) {
        const int hh = t / Fd;
        const int ff = t - hh * Fd;
        float* rp = ss + hh * SS_HEAD + ff * SS_ROW;

        float4 v4[10];
#pragma unroll
        for (int g = 0; g < 10; g++) v4[g] = *(const float4*)(rp + 4 * g);
        float* v = (float*)v4;
        float mx = v[0];
#pragma unroll
        for (int g = 1; g < Fd; g++) mx = fmaxf(mx, v[g]);
        float sum = 0.f;
#pragma unroll
        for (int g = 0; g < Fd; g++) { v[g] = __expf(v[g] - mx); sum += v[g]; }
        float inv = 1.f / sum;
#pragma unroll
        for (int g = 0; g < Fd; g++) v[g] *= inv;
#pragma unroll
        for (int g = 0; g < 10; g++) *(float4*)(rp + 4 * g) = v4[g];
    }
    __syncthreads();

    // ===== out = relu(S @ v + r): tile 5 rows x 4 cols, 4-g stepping ======
    {
        const int rg  = t & 7;
        const int cg  = t >> 3;
        const int o0  = cg * 4;
        const int f0a = rg * 5;
        const int h2  = cg >> 3;

        ull av[5][2];
#pragma unroll
        for (int i = 0; i < 5; i++) {
            ulonglong2 r2 = *(const ulonglong2*)(rs + (f0a + i) * QR_STRIDE + o0);
            av[i][0] = r2.x;
            av[i][1] = r2.y;
        }

        const float* sb = ss + h2 * SS_HEAD;
#pragma unroll 2
        for (int g = 0; g < Fd; g += 4) {
            ulonglong2 va = *(const ulonglong2*)(vs + g * QR_STRIDE + o0);
            ulonglong2 vb = *(const ulonglong2*)(vs + (g + 1) * QR_STRIDE + o0);
            ulonglong2 vc = *(const ulonglong2*)(vs + (g + 2) * QR_STRIDE + o0);
            ulonglong2 vd = *(const ulonglong2*)(vs + (g + 3) * QR_STRIDE + o0);
#pragma unroll
            for (int i = 0; i < 5; i++) {
                float4 s4 = *(const float4*)(sb + (f0a + i) * SS_ROW + g);
                ull sa = pk2(s4.x, s4.x);
                ull sb2 = pk2(s4.y, s4.y);
                ull sc = pk2(s4.z, s4.z);
                ull sd = pk2(s4.w, s4.w);
                av[i][0] = ffma2(sa, va.x, av[i][0]);
                av[i][1] = ffma2(sa, va.y, av[i][1]);
                av[i][0] = ffma2(sb2, vb.x, av[i][0]);
                av[i][1] = ffma2(sb2, vb.y, av[i][1]);
                av[i][0] = ffma2(sc, vc.x, av[i][0]);
                av[i][1] = ffma2(sc, vc.y, av[i][1]);
                av[i][0] = ffma2(sd, vd.x, av[i][0]);
                av[i][1] = ffma2(sd, vd.y, av[i][1]);
            }
        }

        float* ob = out + (size_t)b * (Fd * OUTd);
#pragma unroll
        for (int i = 0; i < 5; i++) {
            float v0, v1, v2, v3;
            unpk2(av[i][0], v0, v1);
            unpk2(av[i][1], v2, v3);
            float4 r4;
            r4.x = fmaxf(v0, 0.f);
            r4.y = fmaxf(v1, 0.f);
            r4.z = fmaxf(v2, 0.f);
            r4.w = fmaxf(v3, 0.f);
            *(float4*)(ob + (f0a + i) * OUTd + o0) = r4;
        }
    }
}

extern "C" void kernel_launch(void* const* d_in, const int* in_sizes, int n_in,
                              void* d_out, int out_size)
{
    const float* x  = (const float*)d_in[0];
    const float* Wq = (const float*)d_in[1];
    const float* bq = (const float*)d_in[2];
    const float* Wk = (const float*)d_in[3];
    const float* bk = (const float*)d_in[4];
    const float* Wv = (const float*)d_in[5];
    const float* bv = (const float*)d_in[6];
    const float* Wr = (const float*)d_in[7];
    const float* br = (const float*)d_in[8];
    float* out = (float*)d_out;

    const int B = in_sizes[0] / (Fd * Ed);

    static int attr_set = 0;
    if (!attr_set) {
        cudaFuncSetAttribute(interacting_layer_kernel,
                             cudaFuncAttributeMaxDynamicSharedMemorySize,
                             SMEM_BYTES);
        attr_set = 1;
    }

    prep_wt_kernel<<<64, 512>>>(Wq, Wk, Wv, Wr);
    interacting_layer_kernel<<<B, 256, SMEM_BYTES>>>(
        x, bq, bk, bv, br, out);
}

// round 17
// speedup vs baseline: 1.0147x; 1.0147x over previous
#include <cuda_runtime.h>

// ---------------------------------------------------------------------------
// InteractingLayer fused kernel v6: v4 structure + register-lean LDS.128
//   - weights in consumption order (quad layout, verified in v5):
//       g_wt[chunk][e2][mat][j][cT][quad]
//   - proj: one ulonglong2 w live at a time (no w[] array -> no spill)
//   - scores: qv[5] + single kv at a time
//   - 256 thr/CTA, 2 CTAs/SM, q/k/v/r + ss overlay the staging region
// ---------------------------------------------------------------------------

#define Fd   40
#define Ed   64
#define OUTd 128

#define XD_STRIDE 136
#define WT_CHUNK  16384                 /* floats: 16 e2-blocks x 1024 */
#define QR_STRIDE 132
#define SS_ROW    44
#define SS_HEAD   1764

/* phase-1 (staging/projection) layout */
#define OFF_XD  0                       /* 40*136 = 5440        */
#define OFF_WTS 5440                    /* 16384 -> end 21824   */
/* phase-2 layout (overlays phase-1; acc carried in regs) */
#define OFF_QS  0
#define OFF_KS  (OFF_QS + Fd * QR_STRIDE)
#define OFF_VS  (OFF_KS + Fd * QR_STRIDE)
#define OFF_RS  (OFF_VS + Fd * QR_STRIDE)
#define OFF_SS  (OFF_RS + Fd * QR_STRIDE)      /* 21120, 4*1764=7056 */
#define SMEM_FLOATS (OFF_SS + 4 * SS_HEAD)     /* 28176 -> 112704 B  */
#define SMEM_BYTES  (SMEM_FLOATS * 4)

typedef unsigned long long ull;

__device__ float g_wt[2 * WT_CHUNK];    /* 128 KB, consumption-ordered */

__device__ __forceinline__ ull pk2(float a, float b) {
    ull r; asm("mov.b64 %0, {%1,%2};" : "=l"(r) : "f"(a), "f"(b)); return r;
}
__device__ __forceinline__ void unpk2(ull v, float& a, float& b) {
    asm("mov.b64 {%0,%1}, %2;" : "=f"(a), "=f"(b) : "l"(v));
}
__device__ __forceinline__ ull ffma2(ull a, ull b, ull c) {
    ull d; asm("fma.rn.f32x2 %0, %1, %2, %3;" : "=l"(d) : "l"(a), "l"(b), "l"(c));
    return d;
}

// ---- prep: consumption-ordered transpose (verified in R15/R16) -------------
// dst = c*16384 + e2*1024 + m*256 + j*32 + cT*4 + eo*2 + p
//   c=e>>5, el=e&31, e2=el>>1, eo=el&1 ; col=2cT+16j+p
__global__ void prep_wt_kernel(const float* __restrict__ Wq,
                               const float* __restrict__ Wk,
                               const float* __restrict__ Wv,
                               const float* __restrict__ Wr)
{
    int i = blockIdx.x * blockDim.x + threadIdx.x;   // 0..32767
    int m   = i >> 13;
    int r   = i & 8191;
    int col = r >> 6;
    int e   = r & 63;
    int c   = e >> 5;
    int el  = e & 31;
    int e2  = el >> 1;
    int eo  = el & 1;
    int j   = col >> 4;
    int cT  = (col & 15) >> 1;
    int p   = col & 1;
    const float* Wm = (m == 0) ? Wq : (m == 1) ? Wk : (m == 2) ? Wv : Wr;
    g_wt[c * WT_CHUNK + e2 * 1024 + m * 256 + j * 32 + cT * 4 + eo * 2 + p]
        = Wm[r];
}

// ---- main fused kernel ------------------------------------------------------
__global__ __launch_bounds__(256, 2)
void interacting_layer_kernel(
    const float* __restrict__ x,
    const float* __restrict__ bq, const float* __restrict__ bk,
    const float* __restrict__ bv, const float* __restrict__ br,
    float* __restrict__ out)
{
    extern __shared__ float sm[];
    float* xd  = sm + OFF_XD;
    float* wts = sm + OFF_WTS;
    float* qs  = sm + OFF_QS;
    float* ks  = sm + OFF_KS;
    float* vs  = sm + OFF_VS;
    float* rs  = sm + OFF_RS;
    float* ss  = sm + OFF_SS;

    const int b = blockIdx.x;
    const int t = threadIdx.x;

    // ===== projection setup: 64 threads/matrix, tile 5 rows x 8 col pairs =
    const int mat = t >> 6;
    const int q2  = t & 63;
    const int f0  = (q2 >> 3) * 5;
    const int cT  = q2 & 7;

    const float* myB = (mat == 0) ? bq : (mat == 1) ? bk : (mat == 2) ? bv : br;
    float*       myO = (mat == 0) ? qs : (mat == 1) ? ks : (mat == 2) ? vs : rs;

    ull acc[5][8];
#pragma unroll
    for (int j = 0; j < 8; j++) {
        float b0 = __ldg(myB + 2 * cT + 16 * j);
        float b1 = __ldg(myB + 2 * cT + 16 * j + 1);
        ull bb = pk2(b0, b1);
#pragma unroll
        for (int i = 0; i < 5; i++) acc[i][j] = bb;
    }

    // ===== two weight chunks: stage -> sync -> accumulate -> sync =========
#pragma unroll 1
    for (int c = 0; c < 2; c++) {
        {
            const float4* gw4 = (const float4*)g_wt + c * (WT_CHUNK / 4);
            float4* wt4 = (float4*)wts;
#pragma unroll
            for (int k = 0; k < WT_CHUNK / 4 / 256; k++)     // 16 iters
                wt4[t + k * 256] = gw4[t + k * 256];
            if (c == 0) {
                const float2* x2 = (const float2*)(x + (size_t)b * (Fd * Ed));
#pragma unroll
                for (int k = 0; k < 5; k++) {
                    int i = t + k * 256;                      // 1280 float2
                    int f  = i >> 5;
                    int ep = i & 31;
                    float2 v = x2[i];
                    float4 d;
                    d.x = v.x; d.y = v.x; d.z = v.y; d.w = v.y;
                    *(float4*)(xd + f * XD_STRIDE + ep * 4) = d;
                }
            }
        }
        __syncthreads();

        const float* myW = wts + mat * 256 + cT * 4;
        const float* myX = xd + f0 * XD_STRIDE + c * 64;
#pragma unroll 1
        for (int e2 = 0; e2 < 16; e2++) {
            ulonglong2 xx[5];
#pragma unroll
            for (int i = 0; i < 5; i++)
                xx[i] = *(const ulonglong2*)(myX + i * XD_STRIDE + e2 * 4);
#pragma unroll
            for (int j = 0; j < 8; j++) {
                ulonglong2 w = *(const ulonglong2*)(myW + e2 * 1024 + j * 32);
#pragma unroll
                for (int i = 0; i < 5; i++)
                    acc[i][j] = ffma2(xx[i].x, w.x, acc[i][j]);
#pragma unroll
                for (int i = 0; i < 5; i++)
                    acc[i][j] = ffma2(xx[i].y, w.y, acc[i][j]);
            }
        }
        __syncthreads();   // after c=1 this also frees xd/wts for overlay
    }

    // ===== write q/k/v/r (overlays staging region) ========================
#pragma unroll
    for (int i = 0; i < 5; i++)
#pragma unroll
        for (int j = 0; j < 8; j++)
            *(ull*)(myO + (f0 + i) * QR_STRIDE + 2 * cT + 16 * j) = acc[i][j];
    __syncthreads();

    // ===== scores: S[h][f][g] = (q.k)/8, 2-dp stepping, lean regs =========
    {
        const int h   = t >> 6;
        const int rst = t & 63;
        const int f0s = (rst >> 3) * 5;
        const int g0  = (rst & 7) * 5;

        ull acc2[5][5];
#pragma unroll
        for (int i = 0; i < 5; i++)
#pragma unroll
            for (int j = 0; j < 5; j++) acc2[i][j] = 0ull;

        const float* qb = qs + h * 32;
        const float* kb = ks + h * 32;
#pragma unroll 1
        for (int dp2 = 0; dp2 < 8; dp2++) {
            ulonglong2 qv[5];
#pragma unroll
            for (int i = 0; i < 5; i++)
                qv[i] = *(const ulonglong2*)(qb + (f0s + i) * QR_STRIDE + 4 * dp2);
#pragma unroll
            for (int j = 0; j < 5; j++) {
                ulonglong2 kv = *(const ulonglong2*)(kb + (g0 + j) * QR_STRIDE + 4 * dp2);
#pragma unroll
                for (int i = 0; i < 5; i++)
                    acc2[i][j] = ffma2(qv[i].x, kv.x, acc2[i][j]);
#pragma unroll
                for (int i = 0; i < 5; i++)
                    acc2[i][j] = ffma2(qv[i].y, kv.y, acc2[i][j]);
            }
        }
#pragma unroll
        for (int i = 0; i < 5; i++)
#pragma unroll
            for (int j = 0; j < 5; j++) {
                float a0, a1;
                unpk2(acc2[i][j], a0, a1);
                ss[h * SS_HEAD + (f0s + i) * SS_ROW + g0 + j] = (a0 + a1) * 0.125f;
            }
    }
    __syncthreads();

    // ===== softmax: 1 thread per row (160 rows), float4 row I/O ===========
    if (t < 160) {
        const int hh = t / Fd;
        const int ff = t - hh * Fd;
        float* rp = ss + hh * SS_HEAD + ff * SS_ROW;

        float4 v4[10];
#pragma unroll
        for (int g = 0; g < 10; g++) v4[g] = *(const float4*)(rp + 4 * g);
        float* v = (float*)v4;
        float mx = v[0];
#pragma unroll
        for (int g = 1; g < Fd; g++) mx = fmaxf(mx, v[g]);
        float sum = 0.f;
#pragma unroll
        for (int g = 0; g < Fd; g++) { v[g] = __expf(v[g] - mx); sum += v[g]; }
        float inv = 1.f / sum;
#pragma unroll
        for (int g = 0; g < Fd; g++) v[g] *= inv;
#pragma unroll
        for (int g = 0; g < 10; g++) *(float4*)(rp + 4 * g) = v4[g];
    }
    __syncthreads();

    // ===== out = relu(S @ v + r): tile 5 rows x 4 cols, 4-g stepping ======
    {
        const int rg  = t & 7;
        const int cg  = t >> 3;
        const int o0  = cg * 4;
        const int f0a = rg * 5;
        const int h2  = cg >> 3;

        ull av[5][2];
#pragma unroll
        for (int i = 0; i < 5; i++) {
            ulonglong2 r2 = *(const ulonglong2*)(rs + (f0a + i) * QR_STRIDE + o0);
            av[i][0] = r2.x;
            av[i][1] = r2.y;
        }

        const float* sb = ss + h2 * SS_HEAD;
#pragma unroll 1
        for (int g = 0; g < Fd; g += 4) {
            ulonglong2 va = *(const ulonglong2*)(vs + g * QR_STRIDE + o0);
            ulonglong2 vb = *(const ulonglong2*)(vs + (g + 1) * QR_STRIDE + o0);
            ulonglong2 vc = *(const ulonglong2*)(vs + (g + 2) * QR_STRIDE + o0);
            ulonglong2 vd = *(const ulonglong2*)(vs + (g + 3) * QR_STRIDE + o0);
#pragma unroll
            for (int i = 0; i < 5; i++) {
                float4 s4 = *(const float4*)(sb + (f0a + i) * SS_ROW + g);
                ull sa  = pk2(s4.x, s4.x);
                ull sb2 = pk2(s4.y, s4.y);
                ull sc  = pk2(s4.z, s4.z);
                ull sd  = pk2(s4.w, s4.w);
                av[i][0] = ffma2(sa, va.x, av[i][0]);
                av[i][1] = ffma2(sa, va.y, av[i][1]);
                av[i][0] = ffma2(sb2, vb.x, av[i][0]);
                av[i][1] = ffma2(sb2, vb.y, av[i][1]);
                av[i][0] = ffma2(sc, vc.x, av[i][0]);
                av[i][1] = ffma2(sc, vc.y, av[i][1]);
                av[i][0] = ffma2(sd, vd.x, av[i][0]);
                av[i][1] = ffma2(sd, vd.y, av[i][1]);
            }
        }

        float* ob = out + (size_t)b * (Fd * OUTd);
#pragma unroll
        for (int i = 0; i < 5; i++) {
            float v0, v1, v2, v3;
            unpk2(av[i][0], v0, v1);
            unpk2(av[i][1], v2, v3);
            float4 r4;
            r4.x = fmaxf(v0, 0.f);
            r4.y = fmaxf(v1, 0.f);
            r4.z = fmaxf(v2, 0.f);
            r4.w = fmaxf(v3, 0.f);
            *(float4*)(ob + (f0a + i) * OUTd + o0) = r4;
        }
    }
}

extern "C" void kernel_launch(void* const* d_in, const int* in_sizes, int n_in,
                              void* d_out, int out_size)
{
    const float* x  = (const float*)d_in[0];
    const float* Wq = (const float*)d_in[1];
    const float* bq = (const float*)d_in[2];
    const float* Wk = (const float*)d_in[3];
    const float* bk = (const float*)d_in[4];
    const float* Wv = (const float*)d_in[5];
    const float* bv = (const float*)d_in[6];
    const float* Wr = (const float*)d_in[7];
    const float* br = (const float*)d_in[8];
    float* out = (float*)d_out;

    const int B = in_sizes[0] / (Fd * Ed);

    static int attr_set = 0;
    if (!attr_set) {
        cudaFuncSetAttribute(interacting_layer_kernel,
                             cudaFuncAttributeMaxDynamicSharedMemorySize,
                             SMEM_BYTES);
        attr_set = 1;
    }

    prep_wt_kernel<<<64, 512>>>(Wq, Wk, Wv, Wr);
    interacting_layer_kernel<<<B, 256, SMEM_BYTES>>>(
        x, bq, bk, bv, br, out);
}